// round 7
// baseline (speedup 1.0000x reference)
#include <cuda_runtime.h>
#include <cuda_bf16.h>
#include <cstdint>
#include <math.h>

#define N_IN   8192
#define N_MC   32768
#define K_TOP  656
#define MASK_WORDS (N_IN / 32)          // 256
#define HPAD   257                      // bank-rotating pad
#define HBINS  65536                    // top-16-bit histogram

__device__ float    g_overlap[N_MC];
__device__ uint32_t g_hist16[HBINS];    // zero at module load; each launch
                                        // overlap adds, topk consumes+rezeros

// ---------------------------------------------------------------------------
// Kernel 1 (fused): mask build + overlap + global top16 histogram
//   overlap_eff[row] = exp(na-dc) * popcount((perm_row >= 0.5) & I)
// 1024 threads/block, one warp per row, float4 .cs streaming (~6.7 TB/s).
// The RED atomics ride free under the DRAM-bound stream.
// ---------------------------------------------------------------------------
__global__ __launch_bounds__(1024) void overlap_kernel(
    const float* __restrict__ I,
    const float* __restrict__ perm,
    const float* __restrict__ duty,
    const float* __restrict__ navg)
{
    __shared__ uint32_t smask[MASK_WORDS];
    const int t    = threadIdx.x;
    const int warp = t >> 5;
    const int lane = t & 31;

    #pragma unroll
    for (int k2 = 0; k2 < 8; ++k2) {
        float v = I[k2 * 1024 + t];
        unsigned ball = __ballot_sync(0xffffffffu, v != 0.0f);
        if (lane == 0) smask[k2 * 32 + warp] = ball;
    }
    __syncthreads();

    const int row = blockIdx.x * 32 + warp;
    const float4* p = reinterpret_cast<const float4*>(perm + (size_t)row * N_IN);

    int cnt = 0;
    #pragma unroll 8
    for (int it = 0; it < 64; ++it) {
        int c4 = it * 32 + lane;
        float4 v = __ldcs(&p[c4]);
        int c = c4 * 4;
        uint32_t m = smask[c >> 5] >> (c & 31);
        cnt += ((m & 1u) && v.x >= 0.5f);
        cnt += ((m & 2u) && v.y >= 0.5f);
        cnt += ((m & 4u) && v.z >= 0.5f);
        cnt += ((m & 8u) && v.w >= 0.5f);
    }
    cnt = __reduce_add_sync(0xffffffffu, cnt);

    if (lane == 0) {
        float d = navg[row] - duty[row];
        float boost = (float)exp((double)d);     // correctly-rounded f32 exp
        float val = boost * (float)cnt;
        g_overlap[row] = val;
        atomicAdd(&g_hist16[__float_as_uint(val) >> 16], 1u);   // RED, no return
    }
}

// ---------------------------------------------------------------------------
// Kernel 2: exact top-K (K=656), jax.lax.top_k tie semantics
// (threshold ties resolved lowest-index-first). Single block, 1024 threads.
// Phase 1: suffix-scan the precomputed 65536-bin top16 histogram -> 16-bit
//          prefix + rem (then re-zero the histogram for the next launch).
// Phase 2: 2 x 8-bit radix passes over register keys (lower 16 bits only),
//          per-warp padded histogram banks.
// Phase 3: register marking with index-ordered tie ranks.
// ---------------------------------------------------------------------------
__global__ __launch_bounds__(1024) void topk_kernel(float* __restrict__ out)
{
    __shared__ uint32_t s_hist[32][HPAD];
    __shared__ uint32_t s_red[256];
    __shared__ uint32_t s_wtot[32];
    __shared__ uint32_t s_prefix;
    __shared__ int      s_rem;

    const int tid  = threadIdx.x;
    const int lane = tid & 31;
    const int wid  = tid >> 5;
    const int seg  = wid << 10;

    // start the 32 key loads early (long-latency, overlapped with the scan)
    uint32_t key[32];
    #pragma unroll
    for (int i = 0; i < 32; ++i)
        key[i] = __float_as_uint(g_overlap[seg + i * 32 + lane]);

    // ---- phase 1: scan g_hist16 in descending bin order ----
    // thread tid covers descending positions [tid*64, tid*64+64)
    uint32_t lsum = 0;
    #pragma unroll
    for (int j = 0; j < 64; ++j)
        lsum += g_hist16[HBINS - 1 - (tid * 64 + j)];

    // block inclusive scan of lsum over tid
    uint32_t inc = lsum;
    #pragma unroll
    for (int off = 1; off < 32; off <<= 1) {
        uint32_t u = __shfl_up_sync(0xffffffffu, inc, off);
        if (lane >= off) inc += u;
    }
    if (lane == 31) s_wtot[wid] = inc;
    __syncthreads();
    if (wid == 0) {
        uint32_t v = s_wtot[lane];
        #pragma unroll
        for (int off = 1; off < 32; off <<= 1) {
            uint32_t u = __shfl_up_sync(0xffffffffu, v, off);
            if (lane >= off) v += u;
        }
        s_wtot[lane] = v;
    }
    __syncthreads();
    inc += (wid == 0) ? 0u : s_wtot[wid - 1];
    uint32_t excl = inc - lsum;

    if ((int)excl < K_TOP && (int)inc >= K_TOP) {   // exactly one thread
        int rem = K_TOP - (int)excl;
        uint32_t cum = 0;
        for (int j = 0; j < 64; ++j) {
            uint32_t b = HBINS - 1 - (tid * 64 + j);
            uint32_t h = g_hist16[b];
            cum += h;
            if ((int)cum >= rem) {
                s_prefix = b << 16;
                s_rem = rem - (int)(cum - h);
                break;
            }
        }
    }

    // zero per-warp banks while waiting (needed by phase 2)
    for (int z = tid; z < 32 * HPAD; z += 1024)
        ((uint32_t*)s_hist)[z] = 0u;
    __syncthreads();

    // re-zero the global histogram (coalesced) for the next launch
    #pragma unroll
    for (int j = 0; j < 64; ++j)
        g_hist16[j * 1024 + tid] = 0u;

    // ---- phase 2: two 8-bit radix passes over the lower 16 bits ----
    for (int shift = 8; shift >= 0; shift -= 8) {
        const uint32_t prefix = s_prefix;

        #pragma unroll
        for (int i = 0; i < 32; ++i) {
            uint32_t k = key[i];
            bool cand = (((k ^ prefix) >> (shift + 8)) == 0u);
            unsigned amask = __ballot_sync(0xffffffffu, cand);
            if (cand) {
                uint32_t bin = (k >> shift) & 255u;
                unsigned peers = __match_any_sync(amask, bin);
                if (lane == (__ffs(peers) - 1))
                    atomicAdd(&s_hist[wid][bin], (uint32_t)__popc(peers));
            }
        }
        __syncthreads();

        if (tid < 256) {
            uint32_t sum = 0;
            #pragma unroll
            for (int w = 0; w < 32; ++w) sum += s_hist[w][tid];
            s_red[tid] = sum;
        }
        __syncthreads();

        if (wid == 0) {
            // suffix-scan over descending bins, 8 bins per lane
            uint32_t loc[8];
            uint32_t csum = 0;
            #pragma unroll
            for (int j = 0; j < 8; ++j) {
                loc[j] = s_red[255 - (lane * 8 + j)];
                csum += loc[j];
            }
            uint32_t winc = csum;
            #pragma unroll
            for (int off = 1; off < 32; off <<= 1) {
                uint32_t u = __shfl_up_sync(0xffffffffu, winc, off);
                if (lane >= off) winc += u;
            }
            uint32_t wexcl = winc - csum;
            int rem = s_rem;
            if ((int)wexcl < rem && (int)winc >= rem) {   // one lane
                uint32_t cum = wexcl;
                #pragma unroll
                for (int j = 0; j < 8; ++j) {
                    cum += loc[j];
                    if ((int)cum >= rem) {
                        uint32_t b = (uint32_t)(255 - (lane * 8 + j));
                        s_prefix = prefix | (b << shift);
                        s_rem = rem - (int)(cum - loc[j]);
                        break;
                    }
                }
            }
        } else if (shift == 8) {
            // zero banks for the second pass
            for (int z = tid - 32; z < 32 * HPAD; z += 992)
                ((uint32_t*)s_hist)[z] = 0u;
        }
        __syncthreads();
    }

    const uint32_t T = s_prefix;   // exact K-th largest key
    const int      r = s_rem;      // # of ==T entries to keep (lowest index)

    // ---- phase 3: marking from registers ----
    int weq = 0;
    #pragma unroll
    for (int i = 0; i < 32; ++i)
        weq += __popc(__ballot_sync(0xffffffffu, key[i] == T));
    if (lane == 0) s_wtot[wid] = (uint32_t)weq;
    __syncthreads();

    if (wid == 0) {
        int v = (int)s_wtot[lane];
        #pragma unroll
        for (int off = 1; off < 32; off <<= 1) {
            int u = __shfl_up_sync(0xffffffffu, v, off);
            if (lane >= off) v += u;
        }
        s_wtot[lane] = (uint32_t)v;
    }
    __syncthreads();

    int rank = (wid == 0) ? 0 : (int)s_wtot[wid - 1];
    #pragma unroll
    for (int i = 0; i < 32; ++i) {
        uint32_t k = key[i];
        bool eq = (k == T);
        unsigned ball = __ballot_sync(0xffffffffu, eq);
        int myrank = rank + __popc(ball & ((1u << lane) - 1u));
        out[seg + i * 32 + lane] = ((k > T) || (eq && myrank < r)) ? 1.0f : 0.0f;
        rank += __popc(ball);
    }
}

// ---------------------------------------------------------------------------
extern "C" void kernel_launch(void* const* d_in, const int* in_sizes, int n_in,
                              void* d_out, int out_size)
{
    const float* I    = (const float*)d_in[0];
    const float* perm = (const float*)d_in[1];
    const float* duty = (const float*)d_in[2];
    const float* navg = (const float*)d_in[3];
    float* out = (float*)d_out;

    (void)in_sizes; (void)n_in; (void)out_size;

    overlap_kernel<<<N_MC / 32, 1024>>>(I, perm, duty, navg);
    topk_kernel<<<1, 1024>>>(out);
}

// round 8
// speedup vs baseline: 1.0020x; 1.0020x over previous
#include <cuda_runtime.h>
#include <cuda_bf16.h>
#include <cstdint>
#include <math.h>

#define N_IN   8192
#define N_MC   32768
#define K_TOP  656
#define MASK_WORDS (N_IN / 32)          // 256
#define HPAD   257                      // bank-rotating pad
#define HBINS  65536                    // top-16-bit histogram (64 rows x 1024)

__device__ float    g_overlap[N_MC];
__device__ uint32_t g_hist16[HBINS];    // zero at load; overlap adds, topk
                                        // consumes and re-zeros each launch

__device__ __forceinline__ uint32_t warp_incl_scan(uint32_t v) {
    #pragma unroll
    for (int off = 1; off < 32; off <<= 1) {
        uint32_t u = __shfl_up_sync(0xffffffffu, v, off);
        if ((threadIdx.x & 31) >= off) v += u;
    }
    return v;
}

// ---------------------------------------------------------------------------
// Kernel 1 (fused): mask build + overlap + global top16 histogram (RED, free)
//   overlap_eff[row] = exp(na-dc) * popcount((perm_row >= 0.5) & I)
// 1024 threads/block, one warp per row, float4 .cs streaming (~6.7 TB/s).
// ---------------------------------------------------------------------------
__global__ __launch_bounds__(1024) void overlap_kernel(
    const float* __restrict__ I,
    const float* __restrict__ perm,
    const float* __restrict__ duty,
    const float* __restrict__ navg)
{
    __shared__ uint32_t smask[MASK_WORDS];
    const int t    = threadIdx.x;
    const int warp = t >> 5;
    const int lane = t & 31;

    #pragma unroll
    for (int k2 = 0; k2 < 8; ++k2) {
        float v = I[k2 * 1024 + t];
        unsigned ball = __ballot_sync(0xffffffffu, v != 0.0f);
        if (lane == 0) smask[k2 * 32 + warp] = ball;
    }
    __syncthreads();

    const int row = blockIdx.x * 32 + warp;
    const float4* p = reinterpret_cast<const float4*>(perm + (size_t)row * N_IN);

    int cnt = 0;
    #pragma unroll 8
    for (int it = 0; it < 64; ++it) {
        int c4 = it * 32 + lane;
        float4 v = __ldcs(&p[c4]);
        int c = c4 * 4;
        uint32_t m = smask[c >> 5] >> (c & 31);
        cnt += ((m & 1u) && v.x >= 0.5f);
        cnt += ((m & 2u) && v.y >= 0.5f);
        cnt += ((m & 4u) && v.z >= 0.5f);
        cnt += ((m & 8u) && v.w >= 0.5f);
    }
    cnt = __reduce_add_sync(0xffffffffu, cnt);

    if (lane == 0) {
        float d = navg[row] - duty[row];
        float boost = (float)exp((double)d);     // correctly-rounded f32 exp
        float val = boost * (float)cnt;
        g_overlap[row] = val;
        atomicAdd(&g_hist16[__float_as_uint(val) >> 16], 1u);   // RED, no return
    }
}

// ---------------------------------------------------------------------------
// Kernel 2: exact top-K (K=656), jax.lax.top_k tie semantics
// (threshold ties lowest-index-first). Single block, 1024 threads.
// Phase 1 (COALESCED): row-sum the 64x1024 hist, suffix-scan rows, scan the
//          one threshold row -> 16-bit prefix + rem; re-zero hist coalesced.
// Phase 2: two 8-bit radix passes over register keys (low 16 bits).
// Phase 3: register marking with index-ordered tie ranks.
// ---------------------------------------------------------------------------
__global__ __launch_bounds__(1024) void topk_kernel(float* __restrict__ out)
{
    __shared__ uint32_t s_hist[32][HPAD];
    __shared__ uint32_t s_red[256];
    __shared__ uint32_t s_row[64];
    __shared__ uint32_t s_wtot[32];
    __shared__ uint32_t s_prefix;
    __shared__ int      s_rem;
    __shared__ int      s_rowpick;
    __shared__ int      s_need;

    const int tid  = threadIdx.x;
    const int lane = tid & 31;
    const int wid  = tid >> 5;
    const int seg  = wid << 10;

    // start key loads early (latency overlapped with phase 1)
    uint32_t key[32];
    #pragma unroll
    for (int i = 0; i < 32; ++i)
        key[i] = __float_as_uint(g_overlap[seg + i * 32 + lane]);

    // ---- phase 1, step A: rowsum[r], warp w handles rows {2w, 2w+1} ----
    #pragma unroll
    for (int rr = 0; rr < 2; ++rr) {
        int r = wid * 2 + rr;
        uint32_t s = 0;
        #pragma unroll
        for (int j = 0; j < 32; ++j)                 // lane-consecutive: 1 line/instr
            s += g_hist16[r * 1024 + j * 32 + lane];
        s = __reduce_add_sync(0xffffffffu, s);
        if (lane == 0) s_row[r] = s;
    }
    __syncthreads();

    // ---- step B: warp 0 suffix-scans rows descending, picks threshold row ----
    if (wid == 0) {
        uint32_t d0 = s_row[63 - lane];              // descending pos p=lane
        uint32_t d1 = s_row[31 - lane];              // p=32+lane
        uint32_t i0 = warp_incl_scan(d0);
        uint32_t tot0 = __shfl_sync(0xffffffffu, i0, 31);
        uint32_t i1 = warp_incl_scan(d1) + tot0;
        uint32_t e0 = i0 - d0, e1 = i1 - d1;
        if (e0 < K_TOP && i0 >= K_TOP) { s_rowpick = 63 - lane; s_need = K_TOP - (int)e0; }
        if (e1 < K_TOP && i1 >= K_TOP) { s_rowpick = 31 - lane; s_need = K_TOP - (int)e1; }
        __syncwarp();

        // ---- step C: scan the threshold row descending (coalesced) ----
        const int r = s_rowpick;
        int need = s_need;
        int acc = 0;
        for (int i = 0; i < 32; ++i) {
            int c = 1023 - (i * 32 + lane);          // lane-consecutive cols
            uint32_t h = g_hist16[r * 1024 + c];
            uint32_t inc = warp_incl_scan(h) + (uint32_t)acc;
            bool cross = ((int)(inc - h) < need && (int)inc >= need);
            unsigned b = __ballot_sync(0xffffffffu, cross);
            if (b) {
                if (cross) {
                    s_prefix = (uint32_t)(r * 1024 + c) << 16;
                    s_rem = need - (int)(inc - h);
                }
                break;
            }
            acc = (int)__shfl_sync(0xffffffffu, inc, 31);
        }
    } else {
        // other warps: zero the per-warp radix banks meanwhile
        for (int z = tid - 32; z < 32 * HPAD; z += 992)
            ((uint32_t*)s_hist)[z] = 0u;
    }
    __syncthreads();

    // re-zero global hist for next launch (coalesced, after all reads)
    #pragma unroll
    for (int j = 0; j < 64; ++j)
        g_hist16[j * 1024 + tid] = 0u;

    // warp 0 didn't help zero the banks; finish any remainder (tiny range)
    if (wid == 0)
        for (int z = tid; z < 32; ++z) ;             // banks fully covered above
    // (warps 1..31 covered [0, 32*HPAD) with stride 992 starting at tid-32>=0)

    // ---- phase 2: two 8-bit radix passes over the low 16 bits ----
    for (int shift = 8; shift >= 0; shift -= 8) {
        const uint32_t prefix = s_prefix;

        #pragma unroll
        for (int i = 0; i < 32; ++i) {
            uint32_t k = key[i];
            bool cand = (((k ^ prefix) >> (shift + 8)) == 0u);
            unsigned amask = __ballot_sync(0xffffffffu, cand);
            if (cand) {
                uint32_t bin = (k >> shift) & 255u;
                unsigned peers = __match_any_sync(amask, bin);
                if (lane == (__ffs(peers) - 1))
                    atomicAdd(&s_hist[wid][bin], (uint32_t)__popc(peers));
            }
        }
        __syncthreads();

        if (tid < 256) {
            uint32_t sum = 0;
            #pragma unroll
            for (int w = 0; w < 32; ++w) sum += s_hist[w][tid];
            s_red[tid] = sum;
        }
        __syncthreads();

        if (wid == 0) {
            uint32_t loc[8];
            uint32_t csum = 0;
            #pragma unroll
            for (int j = 0; j < 8; ++j) {
                loc[j] = s_red[255 - (lane * 8 + j)];
                csum += loc[j];
            }
            uint32_t winc = warp_incl_scan(csum);
            uint32_t wexcl = winc - csum;
            int rem = s_rem;
            if ((int)wexcl < rem && (int)winc >= rem) {
                uint32_t cum = wexcl;
                #pragma unroll
                for (int j = 0; j < 8; ++j) {
                    cum += loc[j];
                    if ((int)cum >= rem) {
                        uint32_t b = (uint32_t)(255 - (lane * 8 + j));
                        s_prefix = prefix | (b << shift);
                        s_rem = rem - (int)(cum - loc[j]);
                        break;
                    }
                }
            }
        } else if (shift == 8) {
            for (int z = tid - 32; z < 32 * HPAD; z += 992)
                ((uint32_t*)s_hist)[z] = 0u;
        }
        __syncthreads();
    }

    const uint32_t T = s_prefix;   // exact K-th largest key
    const int      r = s_rem;      // # of ==T entries to keep (lowest index)

    // ---- phase 3: marking from registers ----
    int weq = 0;
    #pragma unroll
    for (int i = 0; i < 32; ++i)
        weq += __popc(__ballot_sync(0xffffffffu, key[i] == T));
    if (lane == 0) s_wtot[wid] = (uint32_t)weq;
    __syncthreads();

    if (wid == 0) {
        uint32_t v = warp_incl_scan(s_wtot[lane]);
        s_wtot[lane] = v;
    }
    __syncthreads();

    int rank = (wid == 0) ? 0 : (int)s_wtot[wid - 1];
    #pragma unroll
    for (int i = 0; i < 32; ++i) {
        uint32_t k = key[i];
        bool eq = (k == T);
        unsigned ball = __ballot_sync(0xffffffffu, eq);
        int myrank = rank + __popc(ball & ((1u << lane) - 1u));
        out[seg + i * 32 + lane] = ((k > T) || (eq && myrank < r)) ? 1.0f : 0.0f;
        rank += __popc(ball);
    }
}

// ---------------------------------------------------------------------------
extern "C" void kernel_launch(void* const* d_in, const int* in_sizes, int n_in,
                              void* d_out, int out_size)
{
    const float* I    = (const float*)d_in[0];
    const float* perm = (const float*)d_in[1];
    const float* duty = (const float*)d_in[2];
    const float* navg = (const float*)d_in[3];
    float* out = (float*)d_out;

    (void)in_sizes; (void)n_in; (void)out_size;

    overlap_kernel<<<N_MC / 32, 1024>>>(I, perm, duty, navg);
    topk_kernel<<<1, 1024>>>(out);
}

// round 9
// speedup vs baseline: 1.1608x; 1.1585x over previous
#include <cuda_runtime.h>
#include <cuda_bf16.h>
#include <cstdint>
#include <math.h>

#define N_IN   8192
#define N_MC   32768
#define K_TOP  656
#define MASK_WORDS (N_IN / 32)          // 256
#define HPAD   257                      // bank-rotating pad
#define HBINS  65536                    // top-16-bit histogram (64 rows x 1024)

__device__ float    g_overlap[N_MC];
__device__ uint32_t g_hist16[HBINS];    // zero at load; overlap adds, topk
                                        // consumes and re-zeros each launch

__device__ __forceinline__ uint32_t warp_incl_scan(uint32_t v) {
    #pragma unroll
    for (int off = 1; off < 32; off <<= 1) {
        uint32_t u = __shfl_up_sync(0xffffffffu, v, off);
        if ((threadIdx.x & 31) >= off) v += u;
    }
    return v;
}

// ---------------------------------------------------------------------------
// Kernel 1 (fused): mask build + overlap + global top16 histogram (RED, free)
//   overlap_eff[row] = exp(na-dc) * popcount((perm_row >= 0.5) & I)
// 1024 threads/block, one warp per row, float4 .cs streaming (~6.7 TB/s).
// ---------------------------------------------------------------------------
__global__ __launch_bounds__(1024) void overlap_kernel(
    const float* __restrict__ I,
    const float* __restrict__ perm,
    const float* __restrict__ duty,
    const float* __restrict__ navg)
{
    __shared__ uint32_t smask[MASK_WORDS];
    const int t    = threadIdx.x;
    const int warp = t >> 5;
    const int lane = t & 31;

    #pragma unroll
    for (int k2 = 0; k2 < 8; ++k2) {
        float v = I[k2 * 1024 + t];
        unsigned ball = __ballot_sync(0xffffffffu, v != 0.0f);
        if (lane == 0) smask[k2 * 32 + warp] = ball;
    }
    __syncthreads();

    const int row = blockIdx.x * 32 + warp;
    const float4* p = reinterpret_cast<const float4*>(perm + (size_t)row * N_IN);

    int cnt = 0;
    #pragma unroll 8
    for (int it = 0; it < 64; ++it) {
        int c4 = it * 32 + lane;
        float4 v = __ldcs(&p[c4]);
        int c = c4 * 4;
        uint32_t m = smask[c >> 5] >> (c & 31);
        cnt += ((m & 1u) && v.x >= 0.5f);
        cnt += ((m & 2u) && v.y >= 0.5f);
        cnt += ((m & 4u) && v.z >= 0.5f);
        cnt += ((m & 8u) && v.w >= 0.5f);
    }
    cnt = __reduce_add_sync(0xffffffffu, cnt);

    if (lane == 0) {
        float d = navg[row] - duty[row];
        float boost = (float)exp((double)d);     // correctly-rounded f32 exp
        float val = boost * (float)cnt;
        g_overlap[row] = val;
        atomicAdd(&g_hist16[__float_as_uint(val) >> 16], 1u);   // RED, no return
    }
}

// ---------------------------------------------------------------------------
// Kernel 2: exact top-K (K=656), jax.lax.top_k tie semantics
// (threshold ties lowest-index-first). Single block, 1024 threads.
// Phase 1: row-sums (coalesced) -> row pick -> PARALLEL row copy to shared
//          -> group-sum scan (no serialized DRAM chain) -> 16-bit prefix+rem.
// Phase 2: two 8-bit radix passes over register keys (low 16 bits).
// Phase 3: register marking with index-ordered tie ranks.
// ---------------------------------------------------------------------------
__global__ __launch_bounds__(1024) void topk_kernel(float* __restrict__ out)
{
    __shared__ uint32_t s_hist[32][HPAD];
    __shared__ uint32_t s_red[256];
    __shared__ uint32_t s_row[64];      // row sums
    __shared__ uint32_t s_rowcp[1024];  // threshold-row copy
    __shared__ uint32_t s_gs[32];       // group sums of threshold row
    __shared__ uint32_t s_wtot[32];
    __shared__ uint32_t s_prefix;
    __shared__ int      s_rem;
    __shared__ int      s_rowpick;
    __shared__ int      s_need;

    const int tid  = threadIdx.x;
    const int lane = tid & 31;
    const int wid  = tid >> 5;
    const int seg  = wid << 10;

    // keys -> registers early (latency overlapped with phase 1)
    uint32_t key[32];
    #pragma unroll
    for (int i = 0; i < 32; ++i)
        key[i] = __float_as_uint(g_overlap[seg + i * 32 + lane]);

    // zero radix banks up front (reused in phase 2)
    for (int z = tid; z < 32 * HPAD; z += 1024)
        ((uint32_t*)s_hist)[z] = 0u;

    // ---- phase 1, step A: row sums (warp w -> rows {2w, 2w+1}) ----
    #pragma unroll
    for (int rr = 0; rr < 2; ++rr) {
        int r = wid * 2 + rr;
        uint32_t s = 0;
        #pragma unroll
        for (int j = 0; j < 32; ++j)
            s += g_hist16[r * 1024 + j * 32 + lane];   // lane-consecutive
        s = __reduce_add_sync(0xffffffffu, s);
        if (lane == 0) s_row[r] = s;
    }
    __syncthreads();

    // ---- step B: warp 0 suffix-scans rows descending, picks threshold row ----
    if (wid == 0) {
        uint32_t d0 = s_row[63 - lane];
        uint32_t d1 = s_row[31 - lane];
        uint32_t i0 = warp_incl_scan(d0);
        uint32_t tot0 = __shfl_sync(0xffffffffu, i0, 31);
        uint32_t i1 = warp_incl_scan(d1) + tot0;
        uint32_t e0 = i0 - d0, e1 = i1 - d1;
        if (e0 < K_TOP && i0 >= K_TOP) { s_rowpick = 63 - lane; s_need = K_TOP - (int)e0; }
        if (e1 < K_TOP && i1 >= K_TOP) { s_rowpick = 31 - lane; s_need = K_TOP - (int)e1; }
    }
    __syncthreads();

    // ---- step C1: ALL threads copy threshold row to shared (one burst) ----
    const int rpick = s_rowpick;
    s_rowcp[tid] = g_hist16[rpick * 1024 + tid];
    __syncthreads();

    // re-zero global hist for next launch (after all global reads)
    #pragma unroll
    for (int j = 0; j < 64; ++j)
        g_hist16[j * 1024 + tid] = 0u;

    // ---- step C2: group sums in parallel (warp w -> cols [w*32, w*32+32)) ----
    {
        uint32_t v = s_rowcp[wid * 32 + lane];
        v = __reduce_add_sync(0xffffffffu, v);
        if (lane == 0) s_gs[wid] = v;
    }
    __syncthreads();

    // ---- step C3: warp 0 finds threshold column from shared only ----
    if (wid == 0) {
        // scan group sums in DESCENDING group order: desc g -> asc group 31-g
        uint32_t dg = s_gs[31 - lane];
        uint32_t ginc = warp_incl_scan(dg);
        uint32_t gexcl = ginc - dg;
        int need = s_need;
        bool gc = ((int)gexcl < need && (int)ginc >= need);
        unsigned gb = __ballot_sync(0xffffffffu, gc);
        int glane = __ffs(gb) - 1;                      // crossing desc group
        int gstar = 31 - glane;                         // ascending group id
        int need2 = need - (int)__shfl_sync(0xffffffffu, gexcl, glane);

        // within group gstar: descending cols = lanes 31..0
        uint32_t h = s_rowcp[gstar * 32 + (31 - lane)];
        uint32_t inc = warp_incl_scan(h);
        bool cc = ((int)(inc - h) < need2 && (int)inc >= need2);
        if (cc) {                                        // exactly one lane
            int col = gstar * 32 + (31 - lane);
            s_prefix = (uint32_t)(rpick * 1024 + col) << 16;
            s_rem = need2 - (int)(inc - h);
        }
    }
    __syncthreads();

    // ---- phase 2: two 8-bit radix passes over the low 16 bits ----
    for (int shift = 8; shift >= 0; shift -= 8) {
        const uint32_t prefix = s_prefix;

        #pragma unroll
        for (int i = 0; i < 32; ++i) {
            uint32_t k = key[i];
            bool cand = (((k ^ prefix) >> (shift + 8)) == 0u);
            unsigned amask = __ballot_sync(0xffffffffu, cand);
            if (cand) {
                uint32_t bin = (k >> shift) & 255u;
                unsigned peers = __match_any_sync(amask, bin);
                if (lane == (__ffs(peers) - 1))
                    atomicAdd(&s_hist[wid][bin], (uint32_t)__popc(peers));
            }
        }
        __syncthreads();

        if (tid < 256) {
            uint32_t sum = 0;
            #pragma unroll
            for (int w = 0; w < 32; ++w) sum += s_hist[w][tid];
            s_red[tid] = sum;
        }
        __syncthreads();

        if (wid == 0) {
            uint32_t loc[8];
            uint32_t csum = 0;
            #pragma unroll
            for (int j = 0; j < 8; ++j) {
                loc[j] = s_red[255 - (lane * 8 + j)];
                csum += loc[j];
            }
            uint32_t winc = warp_incl_scan(csum);
            uint32_t wexcl = winc - csum;
            int rem = s_rem;
            if ((int)wexcl < rem && (int)winc >= rem) {
                uint32_t cum = wexcl;
                #pragma unroll
                for (int j = 0; j < 8; ++j) {
                    cum += loc[j];
                    if ((int)cum >= rem) {
                        uint32_t b = (uint32_t)(255 - (lane * 8 + j));
                        s_prefix = prefix | (b << shift);
                        s_rem = rem - (int)(cum - loc[j]);
                        break;
                    }
                }
            }
        } else if (shift == 8) {
            // zero banks for the second pass
            for (int z = tid - 32; z < 32 * HPAD; z += 992)
                ((uint32_t*)s_hist)[z] = 0u;
        }
        __syncthreads();
    }

    const uint32_t T = s_prefix;   // exact K-th largest key
    const int      r = s_rem;      // # of ==T entries to keep (lowest index)

    // ---- phase 3: marking from registers ----
    int weq = 0;
    #pragma unroll
    for (int i = 0; i < 32; ++i)
        weq += __popc(__ballot_sync(0xffffffffu, key[i] == T));
    if (lane == 0) s_wtot[wid] = (uint32_t)weq;
    __syncthreads();

    if (wid == 0) s_wtot[lane] = warp_incl_scan(s_wtot[lane]);
    __syncthreads();

    int rank = (wid == 0) ? 0 : (int)s_wtot[wid - 1];
    #pragma unroll
    for (int i = 0; i < 32; ++i) {
        uint32_t k = key[i];
        bool eq = (k == T);
        unsigned ball = __ballot_sync(0xffffffffu, eq);
        int myrank = rank + __popc(ball & ((1u << lane) - 1u));
        out[seg + i * 32 + lane] = ((k > T) || (eq && myrank < r)) ? 1.0f : 0.0f;
        rank += __popc(ball);
    }
}

// ---------------------------------------------------------------------------
extern "C" void kernel_launch(void* const* d_in, const int* in_sizes, int n_in,
                              void* d_out, int out_size)
{
    const float* I    = (const float*)d_in[0];
    const float* perm = (const float*)d_in[1];
    const float* duty = (const float*)d_in[2];
    const float* navg = (const float*)d_in[3];
    float* out = (float*)d_out;

    (void)in_sizes; (void)n_in; (void)out_size;

    overlap_kernel<<<N_MC / 32, 1024>>>(I, perm, duty, navg);
    topk_kernel<<<1, 1024>>>(out);
}

// round 10
// speedup vs baseline: 1.2099x; 1.0423x over previous
#include <cuda_runtime.h>
#include <cuda_bf16.h>
#include <cstdint>
#include <math.h>

#define N_IN   8192
#define N_MC   32768
#define K_TOP  656
#define MASK_WORDS (N_IN / 32)          // 256
#define HPAD   257                      // bank-rotating pad
#define HBINS  65536                    // top-16-bit histogram (64 rows x 1024)

__device__ float    g_overlap[N_MC];
__device__ uint32_t g_hist16[HBINS];    // zero at load; each launch: blocks RED,
                                        // last block consumes and re-zeros
__device__ uint32_t g_done;             // drain ticket; last block resets to 0

__device__ __forceinline__ uint32_t warp_incl_scan(uint32_t v) {
    #pragma unroll
    for (int off = 1; off < 32; off <<= 1) {
        uint32_t u = __shfl_up_sync(0xffffffffu, v, off);
        if ((threadIdx.x & 31) >= off) v += u;
    }
    return v;
}

// ---------------------------------------------------------------------------
// Single fused kernel:
//  * all blocks: mask build + overlap rows + RED into global top16 histogram
//  * LAST block (drain ticket): exact top-K select + marking, inline
//    (jax.lax.top_k tie semantics: threshold ties lowest-index-first)
// ---------------------------------------------------------------------------
__global__ __launch_bounds__(1024) void spatial_pooler_kernel(
    const float* __restrict__ I,
    const float* __restrict__ perm,
    const float* __restrict__ duty,
    const float* __restrict__ navg,
    float* __restrict__ out)
{
    __shared__ uint32_t smask[MASK_WORDS];
    __shared__ uint32_t s_hist[32][HPAD];
    __shared__ uint32_t s_red[256];
    __shared__ uint32_t s_row[64];
    __shared__ uint32_t s_rowcp[1024];
    __shared__ uint32_t s_gs[32];
    __shared__ uint32_t s_wtot[32];
    __shared__ uint32_t s_prefix;
    __shared__ int      s_rem;
    __shared__ int      s_rowpick;
    __shared__ int      s_need;
    __shared__ int      s_islast;

    const int tid  = threadIdx.x;
    const int wid  = tid >> 5;
    const int lane = tid & 31;

    // ---------------- overlap phase (all blocks) ----------------
    #pragma unroll
    for (int k2 = 0; k2 < 8; ++k2) {
        float v = I[k2 * 1024 + tid];
        unsigned ball = __ballot_sync(0xffffffffu, v != 0.0f);
        if (lane == 0) smask[k2 * 32 + wid] = ball;
    }
    __syncthreads();

    {
        const int row = blockIdx.x * 32 + wid;
        const float4* p = reinterpret_cast<const float4*>(perm + (size_t)row * N_IN);

        int cnt = 0;
        #pragma unroll 8
        for (int it = 0; it < 64; ++it) {
            int c4 = it * 32 + lane;
            float4 v = __ldcs(&p[c4]);           // streaming, evict-first
            int c = c4 * 4;
            uint32_t m = smask[c >> 5] >> (c & 31);
            cnt += ((m & 1u) && v.x >= 0.5f);
            cnt += ((m & 2u) && v.y >= 0.5f);
            cnt += ((m & 4u) && v.z >= 0.5f);
            cnt += ((m & 8u) && v.w >= 0.5f);
        }
        cnt = __reduce_add_sync(0xffffffffu, cnt);

        if (lane == 0) {
            float d = navg[row] - duty[row];
            float boost = (float)exp((double)d); // correctly-rounded f32 exp
            float val = boost * (float)cnt;
            g_overlap[row] = val;
            atomicAdd(&g_hist16[__float_as_uint(val) >> 16], 1u);
        }
    }

    // ---------------- drain ticket ----------------
    __threadfence();                             // publish rows + hist REDs
    if (tid == 0) {
        uint32_t ticket = atomicAdd(&g_done, 1u);
        int last = (ticket == gridDim.x - 1);
        if (last) g_done = 0;                    // reset for next graph replay
        s_islast = last;
    }
    __syncthreads();
    if (!s_islast) return;

    // ================ top-K phase (last block only) ================
    const int seg = wid << 10;

    // keys -> registers (L2-hot; overlaps >= 0 so u32 order == float order)
    uint32_t key[32];
    #pragma unroll
    for (int i = 0; i < 32; ++i)
        key[i] = __float_as_uint(g_overlap[seg + i * 32 + lane]);

    // zero radix banks (reused in phase 2)
    for (int z = tid; z < 32 * HPAD; z += 1024)
        ((uint32_t*)s_hist)[z] = 0u;

    // ---- phase 1, step A: row sums (warp w -> rows {2w, 2w+1}) ----
    #pragma unroll
    for (int rr = 0; rr < 2; ++rr) {
        int r = wid * 2 + rr;
        uint32_t s = 0;
        #pragma unroll
        for (int j = 0; j < 32; ++j)
            s += g_hist16[r * 1024 + j * 32 + lane];   // lane-consecutive
        s = __reduce_add_sync(0xffffffffu, s);
        if (lane == 0) s_row[r] = s;
    }
    __syncthreads();

    // ---- step B: warp 0 suffix-scans rows descending, picks row ----
    if (wid == 0) {
        uint32_t d0 = s_row[63 - lane];
        uint32_t d1 = s_row[31 - lane];
        uint32_t i0 = warp_incl_scan(d0);
        uint32_t tot0 = __shfl_sync(0xffffffffu, i0, 31);
        uint32_t i1 = warp_incl_scan(d1) + tot0;
        uint32_t e0 = i0 - d0, e1 = i1 - d1;
        if (e0 < K_TOP && i0 >= K_TOP) { s_rowpick = 63 - lane; s_need = K_TOP - (int)e0; }
        if (e1 < K_TOP && i1 >= K_TOP) { s_rowpick = 31 - lane; s_need = K_TOP - (int)e1; }
    }
    __syncthreads();

    // ---- step C1: all threads copy threshold row to shared (one burst) ----
    const int rpick = s_rowpick;
    s_rowcp[tid] = g_hist16[rpick * 1024 + tid];
    __syncthreads();

    // re-zero global hist for next launch (after all global reads)
    #pragma unroll
    for (int j = 0; j < 64; ++j)
        g_hist16[j * 1024 + tid] = 0u;

    // ---- step C2: group sums (warp w -> cols [w*32, w*32+32)) ----
    {
        uint32_t v = s_rowcp[wid * 32 + lane];
        v = __reduce_add_sync(0xffffffffu, v);
        if (lane == 0) s_gs[wid] = v;
    }
    __syncthreads();

    // ---- step C3: warp 0 finds threshold column from shared ----
    if (wid == 0) {
        uint32_t dg = s_gs[31 - lane];
        uint32_t ginc = warp_incl_scan(dg);
        uint32_t gexcl = ginc - dg;
        int need = s_need;
        bool gc = ((int)gexcl < need && (int)ginc >= need);
        unsigned gb = __ballot_sync(0xffffffffu, gc);
        int glane = __ffs(gb) - 1;
        int gstar = 31 - glane;
        int need2 = need - (int)__shfl_sync(0xffffffffu, gexcl, glane);

        uint32_t h = s_rowcp[gstar * 32 + (31 - lane)];
        uint32_t inc = warp_incl_scan(h);
        bool cc = ((int)(inc - h) < need2 && (int)inc >= need2);
        if (cc) {                                // exactly one lane
            int col = gstar * 32 + (31 - lane);
            s_prefix = (uint32_t)(rpick * 1024 + col) << 16;
            s_rem = need2 - (int)(inc - h);
        }
    }
    __syncthreads();

    // ---- phase 2: two 8-bit radix passes over the low 16 bits ----
    for (int shift = 8; shift >= 0; shift -= 8) {
        const uint32_t prefix = s_prefix;

        #pragma unroll
        for (int i = 0; i < 32; ++i) {
            uint32_t k = key[i];
            bool cand = (((k ^ prefix) >> (shift + 8)) == 0u);
            unsigned amask = __ballot_sync(0xffffffffu, cand);
            if (cand) {
                uint32_t bin = (k >> shift) & 255u;
                unsigned peers = __match_any_sync(amask, bin);
                if (lane == (__ffs(peers) - 1))
                    atomicAdd(&s_hist[wid][bin], (uint32_t)__popc(peers));
            }
        }
        __syncthreads();

        if (tid < 256) {
            uint32_t sum = 0;
            #pragma unroll
            for (int w = 0; w < 32; ++w) sum += s_hist[w][tid];
            s_red[tid] = sum;
        }
        __syncthreads();

        if (wid == 0) {
            uint32_t loc[8];
            uint32_t csum = 0;
            #pragma unroll
            for (int j = 0; j < 8; ++j) {
                loc[j] = s_red[255 - (lane * 8 + j)];
                csum += loc[j];
            }
            uint32_t winc = warp_incl_scan(csum);
            uint32_t wexcl = winc - csum;
            int rem = s_rem;
            if ((int)wexcl < rem && (int)winc >= rem) {
                uint32_t cum = wexcl;
                #pragma unroll
                for (int j = 0; j < 8; ++j) {
                    cum += loc[j];
                    if ((int)cum >= rem) {
                        uint32_t b = (uint32_t)(255 - (lane * 8 + j));
                        s_prefix = prefix | (b << shift);
                        s_rem = rem - (int)(cum - loc[j]);
                        break;
                    }
                }
            }
        } else if (shift == 8) {
            for (int z = tid - 32; z < 32 * HPAD; z += 992)
                ((uint32_t*)s_hist)[z] = 0u;
        }
        __syncthreads();
    }

    const uint32_t T = s_prefix;   // exact K-th largest key
    const int      r = s_rem;      // # of ==T entries to keep (lowest index)

    // ---- phase 3: marking from registers ----
    int weq = 0;
    #pragma unroll
    for (int i = 0; i < 32; ++i)
        weq += __popc(__ballot_sync(0xffffffffu, key[i] == T));
    if (lane == 0) s_wtot[wid] = (uint32_t)weq;
    __syncthreads();

    if (wid == 0) s_wtot[lane] = warp_incl_scan(s_wtot[lane]);
    __syncthreads();

    int rank = (wid == 0) ? 0 : (int)s_wtot[wid - 1];
    #pragma unroll
    for (int i = 0; i < 32; ++i) {
        uint32_t k = key[i];
        bool eq = (k == T);
        unsigned ball = __ballot_sync(0xffffffffu, eq);
        int myrank = rank + __popc(ball & ((1u << lane) - 1u));
        out[seg + i * 32 + lane] = ((k > T) || (eq && myrank < r)) ? 1.0f : 0.0f;
        rank += __popc(ball);
    }
}

// ---------------------------------------------------------------------------
extern "C" void kernel_launch(void* const* d_in, const int* in_sizes, int n_in,
                              void* d_out, int out_size)
{
    const float* I    = (const float*)d_in[0];
    const float* perm = (const float*)d_in[1];
    const float* duty = (const float*)d_in[2];
    const float* navg = (const float*)d_in[3];
    float* out = (float*)d_out;

    (void)in_sizes; (void)n_in; (void)out_size;

    spatial_pooler_kernel<<<N_MC / 32, 1024>>>(I, perm, duty, navg, out);
}